// round 11
// baseline (speedup 1.0000x reference)
#include <cuda_runtime.h>
#include <cstdint>
#include <math.h>

// LSTM cell B=8192, I=H=1024, mma.sync.m16n8k8 tf32.
// Round 8: BM=256 / warp M-tile 64 (mt=4) to amortize B fragments across 4
// MMAs -> smem bytes per MMA drop 192->128. 8 warps, 1 CTA/SM, 3-stage
// cp.async pipeline, fragment-major tf32 scratch from prepasses (unchanged).

#define BATCH  8192
#define HDIM   1024
#define NSTAGE 64
#define STAGE_WORDS 12288                   // 48KB: A 32KB (8192 w) + B 16KB (4096 w)
#define SMEM_WORDS  (3 * STAGE_WORDS + 128)
#define SMEM_BYTES  (SMEM_WORDS * 4)        // 147968

// Fragment-major tf32 scratch.
// gA: [RT=512][kt=256][lane=32][4 words]; word j of lane:
//   j0=(r=16RT+gid, k=8kt+tig) j1=(r+8,k) j2=(r,k+4) j3=(r+8,k+4)
// gB: [g=4][NT=128][kt=256][lane=32][2 words]; (n=8NT+gid, k=8kt+tig+4j)
__device__ __align__(128) uint32_t gA[16777216];   // 64MB
__device__ __align__(128) uint32_t gB[8388608];    // 32MB

__device__ __forceinline__ uint32_t cvt_tf32(float v) {
    uint32_t u; asm("cvt.rna.tf32.f32 %0, %1;" : "=r"(u) : "f"(v)); return u;
}
__device__ __forceinline__ float sigf(float v) { return 1.0f / (1.0f + __expf(-v)); }

__device__ __forceinline__ uint32_t smem_u32(const void* p) {
    uint32_t a;
    asm("{ .reg .u64 t; cvta.to.shared.u64 t, %1; cvt.u32.u64 %0, t; }" : "=r"(a) : "l"(p));
    return a;
}
__device__ __forceinline__ void cpa16(uint32_t sdst, const void* gsrc) {
    asm volatile("cp.async.cg.shared.global [%0], [%1], 16;" :: "r"(sdst), "l"(gsrc) : "memory");
}
__device__ __forceinline__ void mma8(float* c,
                                     uint32_t a0, uint32_t a1, uint32_t a2, uint32_t a3,
                                     uint32_t b0, uint32_t b1) {
    asm volatile("mma.sync.aligned.m16n8k8.row.col.f32.tf32.tf32.f32 "
                 "{%0,%1,%2,%3}, {%4,%5,%6,%7}, {%8,%9}, {%0,%1,%2,%3};"
                 : "+f"(c[0]), "+f"(c[1]), "+f"(c[2]), "+f"(c[3])
                 : "r"(a0), "r"(a1), "r"(a2), "r"(a3), "r"(b0), "r"(b1));
}

// ---------------- prepass A: x|h -> gA ----------------
__global__ void __launch_bounds__(256)
prepA_kernel(const float* __restrict__ x, const float* __restrict__ h)
{
    const uint32_t cid  = blockIdx.x * 256u + threadIdx.x;  // < 4194304
    const uint32_t lane = cid & 31u;
    const uint32_t kt   = (cid >> 5) & 255u;
    const uint32_t RT   = cid >> 13;
    const uint32_t r0   = RT * 16u + (lane >> 2);
    const uint32_t c0   = kt * 8u + (lane & 3u);
    const float* s = (c0 < 1024u) ? x : h;
    const uint32_t cc = c0 & 1023u;
    uint4 o;
    o.x = cvt_tf32(s[(size_t)r0 * 1024 + cc]);
    o.y = cvt_tf32(s[(size_t)(r0 + 8) * 1024 + cc]);
    o.z = cvt_tf32(s[(size_t)r0 * 1024 + cc + 4]);
    o.w = cvt_tf32(s[(size_t)(r0 + 8) * 1024 + cc + 4]);
    *reinterpret_cast<uint4*>(&gA[(size_t)cid * 4]) = o;
}

// ---------------- prepass B: 8 weight mats -> gB ----------------
__global__ void __launch_bounds__(256)
prepB_kernel(const float* __restrict__ wf_i, const float* __restrict__ wf_h,
             const float* __restrict__ wi_i, const float* __restrict__ wi_h,
             const float* __restrict__ wg_i, const float* __restrict__ wg_h,
             const float* __restrict__ wo_i, const float* __restrict__ wo_h)
{
    const uint32_t cb = blockIdx.x * 256u + threadIdx.x;    // < 2097152
    const uint32_t cp = cb & 15u;
    const uint32_t tt = cb >> 4;
    const uint32_t kt = tt & 255u;
    const uint32_t nt = (tt >> 8) & 127u;
    const uint32_t g  = tt >> 15;
    const float* wi = (g == 0) ? wf_i : (g == 1) ? wi_i : (g == 2) ? wg_i : wo_i;
    const float* wh = (g == 0) ? wf_h : (g == 1) ? wi_h : (g == 2) ? wg_h : wo_h;
    uint32_t vals[4];
#pragma unroll
    for (int e = 0; e < 2; e++) {
        const uint32_t l = cp * 2u + e;
        const uint32_t n = nt * 8u + (l >> 2);
#pragma unroll
        for (int j = 0; j < 2; j++) {
            const uint32_t k = kt * 8u + (l & 3u) + 4u * j;
            const float* s = (k < 1024u) ? wi : wh;
            vals[e * 2 + j] = cvt_tf32(s[(size_t)n * 1024 + (k & 1023u)]);
        }
    }
    *reinterpret_cast<uint4*>(&gB[(size_t)cb * 4]) =
        make_uint4(vals[0], vals[1], vals[2], vals[3]);
}

// ---------------- main kernel ----------------
__global__ void __launch_bounds__(256, 1)
lstm_main(const float* __restrict__ c,
          const float* __restrict__ bf_i, const float* __restrict__ bf_h,
          const float* __restrict__ bi_i, const float* __restrict__ bi_h,
          const float* __restrict__ bg_i, const float* __restrict__ bg_h,
          const float* __restrict__ bo_i, const float* __restrict__ bo_h,
          float* __restrict__ out)
{
    extern __shared__ __align__(16) uint32_t smw[];
    const uint32_t sb = smem_u32(smw);
    const int tid = threadIdx.x;
    const int lid = tid & 31;
    const int wid = tid >> 5;
    const int warpM = wid & 3;      // 4 warps in M: 64 rows each
    const int warpN = wid >> 2;     // 2 warps in N: 16 cols each
    const int nb = blockIdx.x;      // 0..31 hidden blocks of 32
    const int mb = blockIdx.y;      // 0..31 batch blocks of 256

    if (tid < 128) {
        const float* bi_tab[4] = {bf_i, bi_i, bg_i, bo_i};
        const float* bh_tab[4] = {bf_h, bi_h, bg_h, bo_h};
        const int g = tid >> 5, j = tid & 31;
        ((float*)(smw + 3 * STAGE_WORDS))[g * 32 + j] =
            bi_tab[g][nb * 32 + j] + bh_tab[g][nb * 32 + j];
    }

    // cp.async mapping: per thread 8 A-chunks + 4 B-chunks of 16B per stage.
    const uint32_t* aSrc[8]; uint32_t aDst[8];
    const uint32_t* bSrc[4]; uint32_t bDst[4];
#pragma unroll
    for (int i = 0; i < 8; i++) {
        const uint32_t ca = (uint32_t)tid * 8u + i;          // 0..2047
        const uint32_t t = ca >> 5, lane16 = ca & 31u;       // A tile 0..63
        const uint32_t rtl = t >> 2, ksl = t & 3u;
        aSrc[i] = gA + (size_t)((((mb * 16u + rtl) * 256u + ksl) * 32u + lane16) * 4u);
        aDst[i] = (t * 128u + lane16 * 4u) * 4u;             // bytes in stage
    }
#pragma unroll
    for (int i = 0; i < 4; i++) {
        const uint32_t cb = (uint32_t)tid * 4u + i;          // 0..1023
        const uint32_t tt = cb >> 4, cp = cb & 15u;
        const uint32_t g = tt >> 4, ntl = (tt >> 2) & 3u, ksb = tt & 3u;
        bSrc[i] = gB + (size_t)((((g * 128u + nb * 4u + ntl) * 256u) + ksb) * 64u + cp * 4u);
        bDst[i] = (8192u + tt * 64u + cp * 4u) * 4u;
    }

#define ISSUE_STAGE(buf_)                                                     \
    do {                                                                      \
        const uint32_t base_ = sb + (uint32_t)(buf_) * (STAGE_WORDS * 4u);    \
        _Pragma("unroll")                                                     \
        for (int i_ = 0; i_ < 8; i_++) {                                      \
            cpa16(base_ + aDst[i_], aSrc[i_]); aSrc[i_] += 512;               \
        }                                                                     \
        _Pragma("unroll")                                                     \
        for (int i_ = 0; i_ < 4; i_++) {                                      \
            cpa16(base_ + bDst[i_], bSrc[i_]); bSrc[i_] += 256;               \
        }                                                                     \
        asm volatile("cp.async.commit_group;" ::: "memory");                  \
    } while (0)

    float acc[4][4][2][4];    // [gate][mt][nt][elem] = 128 accums
#pragma unroll
    for (int g = 0; g < 4; g++)
#pragma unroll
        for (int mt = 0; mt < 4; mt++)
#pragma unroll
            for (int nt = 0; nt < 2; nt++)
#pragma unroll
                for (int e = 0; e < 4; e++) acc[g][mt][nt][e] = 0.0f;

    ISSUE_STAGE(0);
    ISSUE_STAGE(1);
    int bufn = 2;

    for (int s = 0; s < NSTAGE; s++) {
        const int bufc = s % 3;
        if (s < NSTAGE - 1) asm volatile("cp.async.wait_group 1;" ::: "memory");
        else                asm volatile("cp.async.wait_group 0;" ::: "memory");
        __syncthreads();

        // A frag (mt,ks): stage + ((warpM*4+mt)*4+ks)*128 + lid*4 words
        const uint32_t* Ap = smw + bufc * STAGE_WORDS + warpM * 2048 + lid * 4;
        // B frag (g,nt,ks): stage + 8192 + g*1024 + warpN*512 + nt*256 + ks*64 + lid*2
        const uint32_t* Bp = smw + bufc * STAGE_WORDS + 8192 + warpN * 512 + lid * 2;

#pragma unroll
        for (int ks = 0; ks < 4; ks++) {
            uint4 a[4];
#pragma unroll
            for (int mt = 0; mt < 4; mt++)
                a[mt] = *reinterpret_cast<const uint4*>(Ap + mt * 512 + ks * 128);
#pragma unroll
            for (int g = 0; g < 4; g++)
#pragma unroll
                for (int nt = 0; nt < 2; nt++) {
                    const uint2 b = *reinterpret_cast<const uint2*>(
                        Bp + g * 1024 + nt * 256 + ks * 64);
#pragma unroll
                    for (int mt = 0; mt < 4; mt++)
                        mma8(acc[g][mt][nt], a[mt].x, a[mt].y, a[mt].z, a[mt].w, b.x, b.y);
                }
        }

        if (s + 2 < NSTAGE) {
            ISSUE_STAGE(bufn);
            bufn = (bufn == 2) ? 0 : bufn + 1;
        }
    }

    // ---- fused LSTM epilogue ----
    const int gid = lid >> 2;
    const int tig = lid & 3;
    const float* bias_s = (const float*)(smw + 3 * STAGE_WORDS);
    float* outH = out;
    float* outC = out + (size_t)BATCH * HDIM;
    const int mblk = mb * 256;
    const int nblk = nb * 32;

#pragma unroll
    for (int nt = 0; nt < 2; nt++) {
        const int colloc = warpN * 16 + nt * 8 + tig * 2;
        const float bF0 = bias_s[0 * 32 + colloc], bF1 = bias_s[0 * 32 + colloc + 1];
        const float bI0 = bias_s[1 * 32 + colloc], bI1 = bias_s[1 * 32 + colloc + 1];
        const float bG0 = bias_s[2 * 32 + colloc], bG1 = bias_s[2 * 32 + colloc + 1];
        const float bO0 = bias_s[3 * 32 + colloc], bO1 = bias_s[3 * 32 + colloc + 1];
#pragma unroll
        for (int mt = 0; mt < 4; mt++)
#pragma unroll
            for (int p = 0; p < 2; p++) {
                const int m = mblk + warpM * 64 + mt * 16 + gid + 8 * p;
                const size_t base = (size_t)m * HDIM + nblk + colloc;
                const float2 cc = *(const float2*)&c[base];
                const int e = p * 2;
                const float pf0 = acc[0][mt][nt][e] + bF0, pf1 = acc[0][mt][nt][e + 1] + bF1;
                const float pi0 = acc[1][mt][nt][e] + bI0, pi1 = acc[1][mt][nt][e + 1] + bI1;
                const float pg0 = acc[2][mt][nt][e] + bG0, pg1 = acc[2][mt][nt][e + 1] + bG1;
                const float po0 = acc[3][mt][nt][e] + bO0, po1 = acc[3][mt][nt][e + 1] + bO1;
                const float f0 = sigf(pf0), f1 = sigf(pf1);
                const float i0 = sigf(pi0), i1 = sigf(pi1);
                const float g0 = tanhf(pg0), g1 = tanhf(pg1);
                const float o0 = sigf(po0), o1 = sigf(po1);
                const float cn0 = fmaf(f0, cc.x, i0 * g0);
                const float cn1 = fmaf(f1, cc.y, i1 * g1);
                *(float2*)&outH[base] = make_float2(o0 * tanhf(cn0), o1 * tanhf(cn1));
                *(float2*)&outC[base] = make_float2(cn0, cn1);
            }
    }
}

extern "C" void kernel_launch(void* const* d_in, const int* in_sizes, int n_in,
                              void* d_out, int out_size)
{
    const float* x    = (const float*)d_in[0];
    const float* h    = (const float*)d_in[1];
    const float* c    = (const float*)d_in[2];
    const float* wf_i = (const float*)d_in[3];
    const float* bf_i = (const float*)d_in[4];
    const float* wf_h = (const float*)d_in[5];
    const float* bf_h = (const float*)d_in[6];
    const float* wi_i = (const float*)d_in[7];
    const float* bi_i = (const float*)d_in[8];
    const float* wi_h = (const float*)d_in[9];
    const float* bi_h = (const float*)d_in[10];
    const float* wg_i = (const float*)d_in[11];
    const float* bg_i = (const float*)d_in[12];
    const float* wg_h = (const float*)d_in[13];
    const float* bg_h = (const float*)d_in[14];
    const float* wo_i = (const float*)d_in[15];
    const float* bo_i = (const float*)d_in[16];
    const float* wo_h = (const float*)d_in[17];
    const float* bo_h = (const float*)d_in[18];
    float* out = (float*)d_out;

    cudaFuncSetAttribute(lstm_main, cudaFuncAttributeMaxDynamicSharedMemorySize, SMEM_BYTES);

    prepA_kernel<<<16384, 256>>>(x, h);
    prepB_kernel<<<8192, 256>>>(wf_i, wf_h, wi_i, wi_h, wg_i, wg_h, wo_i, wo_h);

    dim3 grid(HDIM / 32, BATCH / 256);   // (32, 32)
    lstm_main<<<grid, 256, SMEM_BYTES>>>(c,
                                         bf_i, bf_h, bi_i, bi_h,
                                         bg_i, bg_h, bo_i, bo_h,
                                         out);
}

// round 12
// speedup vs baseline: 1.1235x; 1.1235x over previous
#include <cuda_runtime.h>
#include <cstdint>
#include <math.h>

// LSTM cell B=8192, I=H=1024, mma.sync.m16n8k8 tf32.
// Round 12: R7 config (BM=128, BNH=32, mt=2, 3-stage cp.async, 2 CTAs/SM)
// + early next-stage issue (before MMA block) + merged prepass kernel.

#define BATCH  8192
#define HDIM   1024
#define NSTAGE 64
#define STAGE_WORDS 8192                    // 32KB per stage (A 16KB + B 16KB)
#define SMEM_WORDS  (3 * STAGE_WORDS + 128)
#define SMEM_BYTES  (SMEM_WORDS * 4)        // 98816

// Fragment-major tf32 scratch.
// gA: [RT=512][kt=256][lane=32][4 words]; word j of lane:
//   j0=(r=16RT+gid, k=8kt+tig) j1=(r+8,k) j2=(r,k+4) j3=(r+8,k+4)
// gB: [g=4][NT=128][kt=256][lane=32][2 words]; (n=8NT+gid, k=8kt+tig+4j)
__device__ __align__(128) uint32_t gA[16777216];   // 64MB
__device__ __align__(128) uint32_t gB[8388608];    // 32MB

__device__ __forceinline__ uint32_t cvt_tf32(float v) {
    uint32_t u; asm("cvt.rna.tf32.f32 %0, %1;" : "=r"(u) : "f"(v)); return u;
}
__device__ __forceinline__ float sigf(float v) { return 1.0f / (1.0f + __expf(-v)); }

__device__ __forceinline__ uint32_t smem_u32(const void* p) {
    uint32_t a;
    asm("{ .reg .u64 t; cvta.to.shared.u64 t, %1; cvt.u32.u64 %0, t; }" : "=r"(a) : "l"(p));
    return a;
}
__device__ __forceinline__ void cpa16(uint32_t sdst, const void* gsrc) {
    asm volatile("cp.async.cg.shared.global [%0], [%1], 16;" :: "r"(sdst), "l"(gsrc) : "memory");
}
__device__ __forceinline__ void mma8(float* c,
                                     uint32_t a0, uint32_t a1, uint32_t a2, uint32_t a3,
                                     uint32_t b0, uint32_t b1) {
    asm volatile("mma.sync.aligned.m16n8k8.row.col.f32.tf32.tf32.f32 "
                 "{%0,%1,%2,%3}, {%4,%5,%6,%7}, {%8,%9}, {%0,%1,%2,%3};"
                 : "+f"(c[0]), "+f"(c[1]), "+f"(c[2]), "+f"(c[3])
                 : "r"(a0), "r"(a1), "r"(a2), "r"(a3), "r"(b0), "r"(b1));
}

// ---------------- merged prepass: x|h -> gA, weights -> gB ----------------
__global__ void __launch_bounds__(256)
prep_kernel(const float* __restrict__ x, const float* __restrict__ h,
            const float* __restrict__ wf_i, const float* __restrict__ wf_h,
            const float* __restrict__ wi_i, const float* __restrict__ wi_h,
            const float* __restrict__ wg_i, const float* __restrict__ wg_h,
            const float* __restrict__ wo_i, const float* __restrict__ wo_h)
{
    if (blockIdx.x < 16384) {
        // ---- A path ----
        const uint32_t cid  = blockIdx.x * 256u + threadIdx.x;  // < 4194304
        const uint32_t lane = cid & 31u;
        const uint32_t kt   = (cid >> 5) & 255u;
        const uint32_t RT   = cid >> 13;
        const uint32_t r0   = RT * 16u + (lane >> 2);
        const uint32_t c0   = kt * 8u + (lane & 3u);
        const float* s = (c0 < 1024u) ? x : h;
        const uint32_t cc = c0 & 1023u;
        uint4 o;
        o.x = cvt_tf32(s[(size_t)r0 * 1024 + cc]);
        o.y = cvt_tf32(s[(size_t)(r0 + 8) * 1024 + cc]);
        o.z = cvt_tf32(s[(size_t)r0 * 1024 + cc + 4]);
        o.w = cvt_tf32(s[(size_t)(r0 + 8) * 1024 + cc + 4]);
        *reinterpret_cast<uint4*>(&gA[(size_t)cid * 4]) = o;
    } else {
        // ---- B path ----
        const uint32_t cb = (blockIdx.x - 16384u) * 256u + threadIdx.x;  // < 2097152
        const uint32_t cp = cb & 15u;
        const uint32_t tt = cb >> 4;
        const uint32_t kt = tt & 255u;
        const uint32_t nt = (tt >> 8) & 127u;
        const uint32_t g  = tt >> 15;
        const float* wi = (g == 0) ? wf_i : (g == 1) ? wi_i : (g == 2) ? wg_i : wo_i;
        const float* wh = (g == 0) ? wf_h : (g == 1) ? wi_h : (g == 2) ? wg_h : wo_h;
        uint32_t vals[4];
#pragma unroll
        for (int e = 0; e < 2; e++) {
            const uint32_t l = cp * 2u + e;
            const uint32_t n = nt * 8u + (l >> 2);
#pragma unroll
            for (int j = 0; j < 2; j++) {
                const uint32_t k = kt * 8u + (l & 3u) + 4u * j;
                const float* s = (k < 1024u) ? wi : wh;
                vals[e * 2 + j] = cvt_tf32(s[(size_t)n * 1024 + (k & 1023u)]);
            }
        }
        *reinterpret_cast<uint4*>(&gB[(size_t)cb * 4]) =
            make_uint4(vals[0], vals[1], vals[2], vals[3]);
    }
}

// ---------------- main kernel ----------------
__global__ void __launch_bounds__(256, 2)
lstm_main(const float* __restrict__ c,
          const float* __restrict__ bf_i, const float* __restrict__ bf_h,
          const float* __restrict__ bi_i, const float* __restrict__ bi_h,
          const float* __restrict__ bg_i, const float* __restrict__ bg_h,
          const float* __restrict__ bo_i, const float* __restrict__ bo_h,
          float* __restrict__ out)
{
    extern __shared__ __align__(16) uint32_t smw[];
    const uint32_t sb = smem_u32(smw);
    const int tid = threadIdx.x;
    const int lid = tid & 31;
    const int wid = tid >> 5;
    const int warpM = wid & 3;
    const int warpN = wid >> 2;
    const int nb = blockIdx.x;     // 0..31 hidden blocks of 32
    const int mb = blockIdx.y;     // 0..63 batch blocks of 128

    if (tid < 128) {
        const float* bi_tab[4] = {bf_i, bi_i, bg_i, bo_i};
        const float* bh_tab[4] = {bf_h, bi_h, bg_h, bo_h};
        const int g = tid >> 5, j = tid & 31;
        ((float*)(smw + 3 * STAGE_WORDS))[g * 32 + j] =
            bi_tab[g][nb * 32 + j] + bh_tab[g][nb * 32 + j];
    }

    // per-thread cp.async sources/dests (4 A chunks + 4 B chunks of 16B per stage)
    const uint32_t* aSrc[4]; uint32_t aDst[4];
    const uint32_t* bSrc[4]; uint32_t bDst[4];
#pragma unroll
    for (int i = 0; i < 4; i++) {
        const uint32_t ca = (uint32_t)tid * 4u + i;          // 0..1023
        const uint32_t t = ca >> 5, lane16 = ca & 31u;
        const uint32_t rtl = t >> 2, ksl = t & 3u;
        aSrc[i] = gA + (size_t)((((mb * 8u + rtl) * 256u + ksl) * 32u + lane16) * 4u);
        aDst[i] = (t * 128u + lane16 * 4u) * 4u;
        const uint32_t tt = ca >> 4, cp = ca & 15u;
        const uint32_t g = tt >> 4, ntl = (tt >> 2) & 3u, ksb = tt & 3u;
        bSrc[i] = gB + (size_t)(((((g * 128u + nb * 4u + ntl) * 256u) + ksb) * 64u + cp * 4u));
        bDst[i] = (4096u + tt * 64u + cp * 4u) * 4u;
    }

#define ISSUE_STAGE(buf_)                                                     \
    do {                                                                      \
        const uint32_t base_ = sb + (uint32_t)(buf_) * 32768u;                \
        _Pragma("unroll")                                                     \
        for (int i_ = 0; i_ < 4; i_++) {                                      \
            cpa16(base_ + aDst[i_], aSrc[i_]); aSrc[i_] += 512;               \
        }                                                                     \
        _Pragma("unroll")                                                     \
        for (int i_ = 0; i_ < 4; i_++) {                                      \
            cpa16(base_ + bDst[i_], bSrc[i_]); bSrc[i_] += 256;               \
        }                                                                     \
        asm volatile("cp.async.commit_group;" ::: "memory");                  \
    } while (0)

    float acc[4][2][2][4];
#pragma unroll
    for (int g = 0; g < 4; g++)
#pragma unroll
        for (int mt = 0; mt < 2; mt++)
#pragma unroll
            for (int nt = 0; nt < 2; nt++)
#pragma unroll
                for (int e = 0; e < 4; e++) acc[g][mt][nt][e] = 0.0f;

    ISSUE_STAGE(0);
    ISSUE_STAGE(1);
    int bufn = 2;

    for (int s = 0; s < NSTAGE; s++) {
        const int bufc = s % 3;
        if (s < NSTAGE - 1) asm volatile("cp.async.wait_group 1;" ::: "memory");
        else                asm volatile("cp.async.wait_group 0;" ::: "memory");
        __syncthreads();

        // EARLY ISSUE: buffer (s+2) was consumed at the (s-1) barrier; start
        // its fill now so loads fly during the MMA block below.
        if (s + 2 < NSTAGE) {
            ISSUE_STAGE(bufn);
            bufn = (bufn == 2) ? 0 : bufn + 1;
        }

        const uint32_t* Ap = smw + bufc * STAGE_WORDS + warpM * 1024 + lid * 4;
        const uint32_t* Bp = smw + bufc * STAGE_WORDS + 4096 + warpN * 512 + lid * 2;

#pragma unroll
        for (int ks = 0; ks < 4; ks++) {
            const uint4 a0 = *reinterpret_cast<const uint4*>(Ap + ks * 128);
            const uint4 a1 = *reinterpret_cast<const uint4*>(Ap + 512 + ks * 128);
#pragma unroll
            for (int g = 0; g < 4; g++)
#pragma unroll
                for (int nt = 0; nt < 2; nt++) {
                    const uint2 b = *reinterpret_cast<const uint2*>(
                        Bp + g * 1024 + nt * 256 + ks * 64);
                    mma8(acc[g][0][nt], a0.x, a0.y, a0.z, a0.w, b.x, b.y);
                    mma8(acc[g][1][nt], a1.x, a1.y, a1.z, a1.w, b.x, b.y);
                }
        }
    }

    // ---- fused LSTM epilogue ----
    const int gid = lid >> 2;
    const int tig = lid & 3;
    const float* bias_s = (const float*)(smw + 3 * STAGE_WORDS);
    float* outH = out;
    float* outC = out + (size_t)BATCH * HDIM;
    const int mblk = mb * 128;
    const int nblk = nb * 32;

#pragma unroll
    for (int nt = 0; nt < 2; nt++) {
        const int colloc = warpN * 16 + nt * 8 + tig * 2;
        const float bF0 = bias_s[0 * 32 + colloc], bF1 = bias_s[0 * 32 + colloc + 1];
        const float bI0 = bias_s[1 * 32 + colloc], bI1 = bias_s[1 * 32 + colloc + 1];
        const float bG0 = bias_s[2 * 32 + colloc], bG1 = bias_s[2 * 32 + colloc + 1];
        const float bO0 = bias_s[3 * 32 + colloc], bO1 = bias_s[3 * 32 + colloc + 1];
#pragma unroll
        for (int mt = 0; mt < 2; mt++)
#pragma unroll
            for (int p = 0; p < 2; p++) {
                const int m = mblk + warpM * 32 + mt * 16 + gid + 8 * p;
                const size_t base = (size_t)m * HDIM + nblk + colloc;
                const float2 cc = *(const float2*)&c[base];
                const int e = p * 2;
                const float pf0 = acc[0][mt][nt][e] + bF0, pf1 = acc[0][mt][nt][e + 1] + bF1;
                const float pi0 = acc[1][mt][nt][e] + bI0, pi1 = acc[1][mt][nt][e + 1] + bI1;
                const float pg0 = acc[2][mt][nt][e] + bG0, pg1 = acc[2][mt][nt][e + 1] + bG1;
                const float po0 = acc[3][mt][nt][e] + bO0, po1 = acc[3][mt][nt][e + 1] + bO1;
                const float f0 = sigf(pf0), f1 = sigf(pf1);
                const float i0 = sigf(pi0), i1 = sigf(pi1);
                const float g0 = tanhf(pg0), g1 = tanhf(pg1);
                const float o0 = sigf(po0), o1 = sigf(po1);
                const float cn0 = fmaf(f0, cc.x, i0 * g0);
                const float cn1 = fmaf(f1, cc.y, i1 * g1);
                *(float2*)&outH[base] = make_float2(o0 * tanhf(cn0), o1 * tanhf(cn1));
                *(float2*)&outC[base] = make_float2(cn0, cn1);
            }
    }
}

extern "C" void kernel_launch(void* const* d_in, const int* in_sizes, int n_in,
                              void* d_out, int out_size)
{
    const float* x    = (const float*)d_in[0];
    const float* h    = (const float*)d_in[1];
    const float* c    = (const float*)d_in[2];
    const float* wf_i = (const float*)d_in[3];
    const float* bf_i = (const float*)d_in[4];
    const float* wf_h = (const float*)d_in[5];
    const float* bf_h = (const float*)d_in[6];
    const float* wi_i = (const float*)d_in[7];
    const float* bi_i = (const float*)d_in[8];
    const float* wi_h = (const float*)d_in[9];
    const float* bi_h = (const float*)d_in[10];
    const float* wg_i = (const float*)d_in[11];
    const float* bg_i = (const float*)d_in[12];
    const float* wg_h = (const float*)d_in[13];
    const float* bg_h = (const float*)d_in[14];
    const float* wo_i = (const float*)d_in[15];
    const float* bo_i = (const float*)d_in[16];
    const float* wo_h = (const float*)d_in[17];
    const float* bo_h = (const float*)d_in[18];
    float* out = (float*)d_out;

    cudaFuncSetAttribute(lstm_main, cudaFuncAttributeMaxDynamicSharedMemorySize, SMEM_BYTES);

    prep_kernel<<<24576, 256>>>(x, h, wf_i, wf_h, wi_i, wi_h, wg_i, wg_h, wo_i, wo_h);

    dim3 grid(HDIM / 32, BATCH / 128);   // (32, 64)
    lstm_main<<<grid, 256, SMEM_BYTES>>>(c,
                                         bf_i, bf_h, bi_i, bi_h,
                                         bg_i, bg_h, bo_i, bo_h,
                                         out);
}

// round 13
// speedup vs baseline: 1.7128x; 1.5245x over previous
#include <cuda_runtime.h>
#include <cstdint>
#include <math.h>

// LSTM cell B=8192, I=H=1024, mma.sync.m16n8k8 tf32.
// Round 13: R7 pipeline (issue AFTER mma), register-slim cp.async addressing
// (2 base pointers + immediate chunk strides), statically unrolled 3-stage
// buffer rotation, merged prepass. 2 CTAs/SM.

#define BATCH  8192
#define HDIM   1024
#define NSTAGE 64
#define STAGE_WORDS 8192                    // 32KB per stage (A 16KB + B 16KB)
#define SMEM_WORDS  (3 * STAGE_WORDS + 128)
#define SMEM_BYTES  (SMEM_WORDS * 4)        // 98816

// Fragment-major tf32 scratch.
// gA: [RT=512][kt=256][lane=32][4 words]; word j of lane:
//   j0=(r=16RT+gid, k=8kt+tig) j1=(r+8,k) j2=(r,k+4) j3=(r+8,k+4)
// gB: [g=4][NT=128][kt=256][lane=32][2 words]; (n=8NT+gid, k=8kt+tig+4j)
__device__ __align__(128) uint32_t gA[16777216];   // 64MB
__device__ __align__(128) uint32_t gB[8388608];    // 32MB

__device__ __forceinline__ uint32_t cvt_tf32(float v) {
    uint32_t u; asm("cvt.rna.tf32.f32 %0, %1;" : "=r"(u) : "f"(v)); return u;
}
__device__ __forceinline__ float sigf(float v) { return 1.0f / (1.0f + __expf(-v)); }

__device__ __forceinline__ uint32_t smem_u32(const void* p) {
    uint32_t a;
    asm("{ .reg .u64 t; cvta.to.shared.u64 t, %1; cvt.u32.u64 %0, t; }" : "=r"(a) : "l"(p));
    return a;
}
__device__ __forceinline__ void cpa16(uint32_t sdst, const void* gsrc) {
    asm volatile("cp.async.cg.shared.global [%0], [%1], 16;" :: "r"(sdst), "l"(gsrc) : "memory");
}
__device__ __forceinline__ void mma8(float* c,
                                     uint32_t a0, uint32_t a1, uint32_t a2, uint32_t a3,
                                     uint32_t b0, uint32_t b1) {
    asm volatile("mma.sync.aligned.m16n8k8.row.col.f32.tf32.tf32.f32 "
                 "{%0,%1,%2,%3}, {%4,%5,%6,%7}, {%8,%9}, {%0,%1,%2,%3};"
                 : "+f"(c[0]), "+f"(c[1]), "+f"(c[2]), "+f"(c[3])
                 : "r"(a0), "r"(a1), "r"(a2), "r"(a3), "r"(b0), "r"(b1));
}

// ---------------- merged prepass: x|h -> gA, weights -> gB ----------------
__global__ void __launch_bounds__(256)
prep_kernel(const float* __restrict__ x, const float* __restrict__ h,
            const float* __restrict__ wf_i, const float* __restrict__ wf_h,
            const float* __restrict__ wi_i, const float* __restrict__ wi_h,
            const float* __restrict__ wg_i, const float* __restrict__ wg_h,
            const float* __restrict__ wo_i, const float* __restrict__ wo_h)
{
    if (blockIdx.x < 16384) {
        const uint32_t cid  = blockIdx.x * 256u + threadIdx.x;
        const uint32_t lane = cid & 31u;
        const uint32_t kt   = (cid >> 5) & 255u;
        const uint32_t RT   = cid >> 13;
        const uint32_t r0   = RT * 16u + (lane >> 2);
        const uint32_t c0   = kt * 8u + (lane & 3u);
        const float* s = (c0 < 1024u) ? x : h;
        const uint32_t cc = c0 & 1023u;
        uint4 o;
        o.x = cvt_tf32(s[(size_t)r0 * 1024 + cc]);
        o.y = cvt_tf32(s[(size_t)(r0 + 8) * 1024 + cc]);
        o.z = cvt_tf32(s[(size_t)r0 * 1024 + cc + 4]);
        o.w = cvt_tf32(s[(size_t)(r0 + 8) * 1024 + cc + 4]);
        *reinterpret_cast<uint4*>(&gA[(size_t)cid * 4]) = o;
    } else {
        const uint32_t cb = (blockIdx.x - 16384u) * 256u + threadIdx.x;
        const uint32_t cp = cb & 15u;
        const uint32_t tt = cb >> 4;
        const uint32_t kt = tt & 255u;
        const uint32_t nt = (tt >> 8) & 127u;
        const uint32_t g  = tt >> 15;
        const float* wi = (g == 0) ? wf_i : (g == 1) ? wi_i : (g == 2) ? wg_i : wo_i;
        const float* wh = (g == 0) ? wf_h : (g == 1) ? wi_h : (g == 2) ? wg_h : wo_h;
        uint32_t vals[4];
#pragma unroll
        for (int e = 0; e < 2; e++) {
            const uint32_t l = cp * 2u + e;
            const uint32_t n = nt * 8u + (l >> 2);
#pragma unroll
            for (int j = 0; j < 2; j++) {
                const uint32_t k = kt * 8u + (l & 3u) + 4u * j;
                const float* s = (k < 1024u) ? wi : wh;
                vals[e * 2 + j] = cvt_tf32(s[(size_t)n * 1024 + (k & 1023u)]);
            }
        }
        *reinterpret_cast<uint4*>(&gB[(size_t)cb * 4]) =
            make_uint4(vals[0], vals[1], vals[2], vals[3]);
    }
}

// ---------------- main kernel ----------------
__global__ void __launch_bounds__(256, 2)
lstm_main(const float* __restrict__ c,
          const float* __restrict__ bf_i, const float* __restrict__ bf_h,
          const float* __restrict__ bi_i, const float* __restrict__ bi_h,
          const float* __restrict__ bg_i, const float* __restrict__ bg_h,
          const float* __restrict__ bo_i, const float* __restrict__ bo_h,
          float* __restrict__ out)
{
    extern __shared__ __align__(16) uint32_t smw[];
    const uint32_t sb = smem_u32(smw);
    const int tid = threadIdx.x;
    const int lid = tid & 31;
    const int wid = tid >> 5;
    const int warpM = wid & 3;
    const int warpN = wid >> 2;
    const int nb = blockIdx.x;     // 0..31 hidden blocks of 32
    const int mb = blockIdx.y;     // 0..63 batch blocks of 128

    if (tid < 128) {
        const float* bi_tab[4] = {bf_i, bi_i, bg_i, bo_i};
        const float* bh_tab[4] = {bf_h, bi_h, bg_h, bo_h};
        const int g = tid >> 5, j = tid & 31;
        ((float*)(smw + 3 * STAGE_WORDS))[g * 32 + j] =
            bi_tab[g][nb * 32 + j] + bh_tab[g][nb * 32 + j];
    }

    // Chunk mapping ca/cb = tid + 256*i  ->  all chunk offsets linear in i.
    // A chunk i: src byte = aBase + i*262144, dst = stagebase + aDstOff + i*4096
    // B chunk i: src byte = bBase + i*8388608, dst = stagebase + bDstOff + i*4096
    const uint32_t t0 = (uint32_t)tid >> 5;
    const char* aSrcB = (const char*)gA +
        (size_t)((((uint32_t)mb * 8u + (t0 >> 2)) * 256u + (t0 & 3u)) * 128u +
                 ((uint32_t)tid & 31u) * 4u) * 4u;
    const char* bSrcB = (const char*)gB +
        (size_t)((((uint32_t)nb * 4u + (((uint32_t)tid >> 6) & 3u)) * 256u +
                  (((uint32_t)tid >> 4) & 3u)) * 64u + ((uint32_t)tid & 15u) * 4u) * 4u;
    const uint32_t aDstOff = t0 * 512u + ((uint32_t)tid & 31u) * 16u;
    const uint32_t bDstOff = 16384u + (((uint32_t)tid >> 4) & 15u) * 256u +
                             ((uint32_t)tid & 15u) * 16u;

#define ISSUE(BUF_)                                                           \
    do {                                                                      \
        const uint32_t da_ = sb + (BUF_) * 32768u + aDstOff;                  \
        const uint32_t db_ = sb + (BUF_) * 32768u + bDstOff;                  \
        cpa16(da_,          aSrcB);                                           \
        cpa16(da_ + 4096u,  aSrcB + 262144);                                  \
        cpa16(da_ + 8192u,  aSrcB + 524288);                                  \
        cpa16(da_ + 12288u, aSrcB + 786432);                                  \
        cpa16(db_,          bSrcB);                                           \
        cpa16(db_ + 4096u,  bSrcB + 8388608);                                 \
        cpa16(db_ + 8192u,  bSrcB + 16777216);                                \
        cpa16(db_ + 12288u, bSrcB + 25165824);                                \
        asm volatile("cp.async.commit_group;" ::: "memory");                  \
        aSrcB += 2048;                                                        \
        bSrcB += 1024;                                                        \
    } while (0)

    float acc[4][2][2][4];
#pragma unroll
    for (int g = 0; g < 4; g++)
#pragma unroll
        for (int mt = 0; mt < 2; mt++)
#pragma unroll
            for (int nt = 0; nt < 2; nt++)
#pragma unroll
                for (int e = 0; e < 4; e++) acc[g][mt][nt][e] = 0.0f;

#define MMA_BLOCK(BUF_)                                                       \
    do {                                                                      \
        const uint32_t* Ap_ = smw + (BUF_) * STAGE_WORDS + warpM * 1024 + lid * 4; \
        const uint32_t* Bp_ = smw + (BUF_) * STAGE_WORDS + 4096 + warpN * 512 + lid * 2; \
        _Pragma("unroll")                                                     \
        for (int ks_ = 0; ks_ < 4; ks_++) {                                   \
            const uint4 a0_ = *reinterpret_cast<const uint4*>(Ap_ + ks_ * 128);       \
            const uint4 a1_ = *reinterpret_cast<const uint4*>(Ap_ + 512 + ks_ * 128); \
            _Pragma("unroll")                                                 \
            for (int g_ = 0; g_ < 4; g_++)                                    \
                _Pragma("unroll")                                             \
                for (int nt_ = 0; nt_ < 2; nt_++) {                           \
                    const uint2 b_ = *reinterpret_cast<const uint2*>(         \
                        Bp_ + g_ * 1024 + nt_ * 256 + ks_ * 64);              \
                    mma8(acc[g_][0][nt_], a0_.x, a0_.y, a0_.z, a0_.w, b_.x, b_.y); \
                    mma8(acc[g_][1][nt_], a1_.x, a1_.y, a1_.z, a1_.w, b_.x, b_.y); \
                }                                                             \
        }                                                                     \
    } while (0)

#define WAIT1() asm volatile("cp.async.wait_group 1;" ::: "memory")
#define WAIT0() asm volatile("cp.async.wait_group 0;" ::: "memory")

    ISSUE(0);
    ISSUE(1);

    // stages 0..62 as 21 static triples; issue AFTER mma (R7 ordering).
    for (int su = 0; su < 21; su++) {
        WAIT1(); __syncthreads();
        MMA_BLOCK(0);
        ISSUE(2);                      // stage 3su+2 -> buf2
        WAIT1(); __syncthreads();
        MMA_BLOCK(1);
        ISSUE(0);                      // stage 3su+3 -> buf0
        WAIT1(); __syncthreads();
        MMA_BLOCK(2);
        if (su < 20) ISSUE(1);         // stage 3su+4 -> buf1 (last valid: 63)
    }
    // tail: stage 63 lives in buf0
    WAIT0(); __syncthreads();
    MMA_BLOCK(0);

    // ---- fused LSTM epilogue ----
    const int gid = lid >> 2;
    const int tig = lid & 3;
    const float* bias_s = (const float*)(smw + 3 * STAGE_WORDS);
    float* outH = out;
    float* outC = out + (size_t)BATCH * HDIM;
    const int mblk = mb * 128;
    const int nblk = nb * 32;

#pragma unroll
    for (int nt = 0; nt < 2; nt++) {
        const int colloc = warpN * 16 + nt * 8 + tig * 2;
        const float bF0 = bias_s[0 * 32 + colloc], bF1 = bias_s[0 * 32 + colloc + 1];
        const float bI0 = bias_s[1 * 32 + colloc], bI1 = bias_s[1 * 32 + colloc + 1];
        const float bG0 = bias_s[2 * 32 + colloc], bG1 = bias_s[2 * 32 + colloc + 1];
        const float bO0 = bias_s[3 * 32 + colloc], bO1 = bias_s[3 * 32 + colloc + 1];
#pragma unroll
        for (int mt = 0; mt < 2; mt++)
#pragma unroll
            for (int p = 0; p < 2; p++) {
                const int m = mblk + warpM * 32 + mt * 16 + gid + 8 * p;
                const size_t base = (size_t)m * HDIM + nblk + colloc;
                const float2 cc = *(const float2*)&c[base];
                const int e = p * 2;
                const float pf0 = acc[0][mt][nt][e] + bF0, pf1 = acc[0][mt][nt][e + 1] + bF1;
                const float pi0 = acc[1][mt][nt][e] + bI0, pi1 = acc[1][mt][nt][e + 1] + bI1;
                const float pg0 = acc[2][mt][nt][e] + bG0, pg1 = acc[2][mt][nt][e + 1] + bG1;
                const float po0 = acc[3][mt][nt][e] + bO0, po1 = acc[3][mt][nt][e + 1] + bO1;
                const float f0 = sigf(pf0), f1 = sigf(pf1);
                const float i0 = sigf(pi0), i1 = sigf(pi1);
                const float g0 = tanhf(pg0), g1 = tanhf(pg1);
                const float o0 = sigf(po0), o1 = sigf(po1);
                const float cn0 = fmaf(f0, cc.x, i0 * g0);
                const float cn1 = fmaf(f1, cc.y, i1 * g1);
                *(float2*)&outH[base] = make_float2(o0 * tanhf(cn0), o1 * tanhf(cn1));
                *(float2*)&outC[base] = make_float2(cn0, cn1);
            }
    }
}

extern "C" void kernel_launch(void* const* d_in, const int* in_sizes, int n_in,
                              void* d_out, int out_size)
{
    const float* x    = (const float*)d_in[0];
    const float* h    = (const float*)d_in[1];
    const float* c    = (const float*)d_in[2];
    const float* wf_i = (const float*)d_in[3];
    const float* bf_i = (const float*)d_in[4];
    const float* wf_h = (const float*)d_in[5];
    const float* bf_h = (const float*)d_in[6];
    const float* wi_i = (const float*)d_in[7];
    const float* bi_i = (const float*)d_in[8];
    const float* wi_h = (const float*)d_in[9];
    const float* bi_h = (const float*)d_in[10];
    const float* wg_i = (const float*)d_in[11];
    const float* bg_i = (const float*)d_in[12];
    const float* wg_h = (const float*)d_in[13];
    const float* bg_h = (const float*)d_in[14];
    const float* wo_i = (const float*)d_in[15];
    const float* bo_i = (const float*)d_in[16];
    const float* wo_h = (const float*)d_in[17];
    const float* bo_h = (const float*)d_in[18];
    float* out = (float*)d_out;

    cudaFuncSetAttribute(lstm_main, cudaFuncAttributeMaxDynamicSharedMemorySize, SMEM_BYTES);

    prep_kernel<<<24576, 256>>>(x, h, wf_i, wf_h, wi_i, wi_h, wg_i, wg_h, wo_i, wo_h);

    dim3 grid(HDIM / 32, BATCH / 128);   // (32, 64)
    lstm_main<<<grid, 256, SMEM_BYTES>>>(c,
                                         bf_i, bf_h, bi_i, bi_h,
                                         bg_i, bg_h, bo_i, bo_h,
                                         out);
}

// round 14
// speedup vs baseline: 1.7813x; 1.0400x over previous
#include <cuda_runtime.h>
#include <cstdint>
#include <math.h>

// LSTM cell B=8192, I=H=1024, mma.sync.m16n8k8 tf32.
// Round 14: R13 + gate-paired gB layout (B frags via LDS.128, fragment issue
// count 40->24 per warp-stage) + MUFU tanh.approx epilogue.

#define BATCH  8192
#define HDIM   1024
#define NSTAGE 64
#define STAGE_WORDS 8192                    // 32KB per stage (A 16KB + B 16KB)
#define SMEM_WORDS  (3 * STAGE_WORDS + 128)
#define SMEM_BYTES  (SMEM_WORDS * 4)        // 98816

// Fragment-major tf32 scratch.
// gA: [RT=512][kt=256][lane=32][4 words]; word j of lane:
//   j0=(r=16RT+gid, k=8kt+tig) j1=(r+8,k) j2=(r,k+4) j3=(r+8,k+4)
// gB (gate-paired): [gp=2][NT=128][kt=256][lane=32][4 words]:
//   w0=(g=2gp,  n=8NT+gid, k=8kt+tig) w1=(g=2gp,  k+4)
//   w2=(g=2gp+1,n,k)                  w3=(g=2gp+1,k+4)
__device__ __align__(128) uint32_t gA[16777216];   // 64MB
__device__ __align__(128) uint32_t gB[8388608];    // 32MB

__device__ __forceinline__ uint32_t cvt_tf32(float v) {
    uint32_t u; asm("cvt.rna.tf32.f32 %0, %1;" : "=r"(u) : "f"(v)); return u;
}
__device__ __forceinline__ float tanh_ap(float x) {
    float y; asm("tanh.approx.f32 %0, %1;" : "=f"(y) : "f"(x)); return y;
}
__device__ __forceinline__ float sig_ap(float x) {
    return fmaf(0.5f, tanh_ap(0.5f * x), 0.5f);
}

__device__ __forceinline__ uint32_t smem_u32(const void* p) {
    uint32_t a;
    asm("{ .reg .u64 t; cvta.to.shared.u64 t, %1; cvt.u32.u64 %0, t; }" : "=r"(a) : "l"(p));
    return a;
}
__device__ __forceinline__ void cpa16(uint32_t sdst, const void* gsrc) {
    asm volatile("cp.async.cg.shared.global [%0], [%1], 16;" :: "r"(sdst), "l"(gsrc) : "memory");
}
__device__ __forceinline__ void mma8(float* c,
                                     uint32_t a0, uint32_t a1, uint32_t a2, uint32_t a3,
                                     uint32_t b0, uint32_t b1) {
    asm volatile("mma.sync.aligned.m16n8k8.row.col.f32.tf32.tf32.f32 "
                 "{%0,%1,%2,%3}, {%4,%5,%6,%7}, {%8,%9}, {%0,%1,%2,%3};"
                 : "+f"(c[0]), "+f"(c[1]), "+f"(c[2]), "+f"(c[3])
                 : "r"(a0), "r"(a1), "r"(a2), "r"(a3), "r"(b0), "r"(b1));
}

// ---------------- merged prepass: x|h -> gA, weights -> gB ----------------
__global__ void __launch_bounds__(256)
prep_kernel(const float* __restrict__ x, const float* __restrict__ h,
            const float* __restrict__ wf_i, const float* __restrict__ wf_h,
            const float* __restrict__ wi_i, const float* __restrict__ wi_h,
            const float* __restrict__ wg_i, const float* __restrict__ wg_h,
            const float* __restrict__ wo_i, const float* __restrict__ wo_h)
{
    if (blockIdx.x < 16384) {
        const uint32_t cid  = blockIdx.x * 256u + threadIdx.x;
        const uint32_t lane = cid & 31u;
        const uint32_t kt   = (cid >> 5) & 255u;
        const uint32_t RT   = cid >> 13;
        const uint32_t r0   = RT * 16u + (lane >> 2);
        const uint32_t c0   = kt * 8u + (lane & 3u);
        const float* s = (c0 < 1024u) ? x : h;
        const uint32_t cc = c0 & 1023u;
        uint4 o;
        o.x = cvt_tf32(s[(size_t)r0 * 1024 + cc]);
        o.y = cvt_tf32(s[(size_t)(r0 + 8) * 1024 + cc]);
        o.z = cvt_tf32(s[(size_t)r0 * 1024 + cc + 4]);
        o.w = cvt_tf32(s[(size_t)(r0 + 8) * 1024 + cc + 4]);
        *reinterpret_cast<uint4*>(&gA[(size_t)cid * 4]) = o;
    } else {
        const uint32_t cb   = (blockIdx.x - 16384u) * 256u + threadIdx.x;  // < 2097152
        const uint32_t lane = cb & 31u;
        const uint32_t kt   = (cb >> 5) & 255u;
        const uint32_t NT   = (cb >> 13) & 127u;
        const uint32_t gp   = cb >> 20;                       // 0..1
        const uint32_t n    = NT * 8u + (lane >> 2);
        const uint32_t k    = kt * 8u + (lane & 3u);          // k, k+4 in same half
        const float* w0 = (gp == 0) ? ((k < 1024u) ? wf_i : wf_h)
                                    : ((k < 1024u) ? wg_i : wg_h);
        const float* w1 = (gp == 0) ? ((k < 1024u) ? wi_i : wi_h)
                                    : ((k < 1024u) ? wo_i : wo_h);
        const uint32_t kk = k & 1023u;
        uint4 o;
        o.x = cvt_tf32(w0[(size_t)n * 1024 + kk]);
        o.y = cvt_tf32(w0[(size_t)n * 1024 + kk + 4]);
        o.z = cvt_tf32(w1[(size_t)n * 1024 + kk]);
        o.w = cvt_tf32(w1[(size_t)n * 1024 + kk + 4]);
        *reinterpret_cast<uint4*>(&gB[(size_t)cb * 4]) = o;
    }
}

// ---------------- main kernel ----------------
__global__ void __launch_bounds__(256, 2)
lstm_main(const float* __restrict__ c,
          const float* __restrict__ bf_i, const float* __restrict__ bf_h,
          const float* __restrict__ bi_i, const float* __restrict__ bi_h,
          const float* __restrict__ bg_i, const float* __restrict__ bg_h,
          const float* __restrict__ bo_i, const float* __restrict__ bo_h,
          float* __restrict__ out)
{
    extern __shared__ __align__(16) uint32_t smw[];
    const uint32_t sb = smem_u32(smw);
    const int tid = threadIdx.x;
    const int lid = tid & 31;
    const int wid = tid >> 5;
    const int warpM = wid & 3;
    const int warpN = wid >> 2;
    const int nb = blockIdx.x;     // 0..31 hidden blocks of 32
    const int mb = blockIdx.y;     // 0..63 batch blocks of 128

    if (tid < 128) {
        const float* bi_tab[4] = {bf_i, bi_i, bg_i, bo_i};
        const float* bh_tab[4] = {bf_h, bi_h, bg_h, bo_h};
        const int g = tid >> 5, j = tid & 31;
        ((float*)(smw + 3 * STAGE_WORDS))[g * 32 + j] =
            bi_tab[g][nb * 32 + j] + bh_tab[g][nb * 32 + j];
    }

    // ---- cp.async addressing (2 base pointers + immediate chunk strides) ----
    // A (unchanged): chunk i stride 262144B, per stage +2048B.
    const uint32_t t0 = (uint32_t)tid >> 5;
    const char* aSrcB = (const char*)gA +
        (size_t)((((uint32_t)mb * 8u + (t0 >> 2)) * 256u + (t0 & 3u)) * 128u +
                 ((uint32_t)tid & 31u) * 4u) * 4u;
    const uint32_t aDstOff = t0 * 512u + ((uint32_t)tid & 31u) * 16u;

    // B (gate-paired): thread covers lane(5b), kts(2b), ntl-low(1b); chunk i:
    // bit0 -> ntl-high (+262144B), bit1 -> gp (+16777216B). Per stage +2048B.
    const char* bSrcB = (const char*)gB +
        (size_t)((((uint32_t)nb * 4u + ((uint32_t)tid >> 7)) * 256u +
                  (((uint32_t)tid >> 5) & 3u)) * 128u + ((uint32_t)tid & 31u) * 4u) * 4u;
    const uint32_t bDstOff = 16384u + ((uint32_t)tid >> 7) * 2048u +
                             (((uint32_t)tid >> 5) & 3u) * 512u +
                             ((uint32_t)tid & 31u) * 16u;

#define ISSUE(BUF_)                                                           \
    do {                                                                      \
        const uint32_t da_ = sb + (BUF_) * 32768u + aDstOff;                  \
        const uint32_t db_ = sb + (BUF_) * 32768u + bDstOff;                  \
        cpa16(da_,          aSrcB);                                           \
        cpa16(da_ + 4096u,  aSrcB + 262144);                                  \
        cpa16(da_ + 8192u,  aSrcB + 524288);                                  \
        cpa16(da_ + 12288u, aSrcB + 786432);                                  \
        cpa16(db_,          bSrcB);                                           \
        cpa16(db_ + 4096u,  bSrcB + 262144);                                  \
        cpa16(db_ + 8192u,  bSrcB + 16777216);                                \
        cpa16(db_ + 12288u, bSrcB + 17039360);                                \
        asm volatile("cp.async.commit_group;" ::: "memory");                  \
        aSrcB += 2048;                                                        \
        bSrcB += 2048;                                                        \
    } while (0)

    float acc[4][2][2][4];
#pragma unroll
    for (int g = 0; g < 4; g++)
#pragma unroll
        for (int mt = 0; mt < 2; mt++)
#pragma unroll
            for (int nt = 0; nt < 2; nt++)
#pragma unroll
                for (int e = 0; e < 4; e++) acc[g][mt][nt][e] = 0.0f;

    // B frag words within stage: 4096 + gp*2048 + ntl*512 + ks*128 + lid*4
    // where ntl = warpN*2 + nt. gates (2gp, 2gp+1) come from one uint4.
#define MMA_BLOCK(BUF_)                                                       \
    do {                                                                      \
        const uint32_t* Ap_ = smw + (BUF_) * STAGE_WORDS + warpM * 1024 + lid * 4; \
        const uint32_t* Bp_ = smw + (BUF_) * STAGE_WORDS + 4096 + warpN * 1024 + lid * 4; \
        _Pragma("unroll")                                                     \
        for (int ks_ = 0; ks_ < 4; ks_++) {                                   \
            const uint4 a0_ = *reinterpret_cast<const uint4*>(Ap_ + ks_ * 128);       \
            const uint4 a1_ = *reinterpret_cast<const uint4*>(Ap_ + 512 + ks_ * 128); \
            _Pragma("unroll")                                                 \
            for (int nt_ = 0; nt_ < 2; nt_++) {                               \
                const uint4 b01_ = *reinterpret_cast<const uint4*>(           \
                    Bp_ + nt_ * 512 + ks_ * 128);                             \
                const uint4 b23_ = *reinterpret_cast<const uint4*>(           \
                    Bp_ + 2048 + nt_ * 512 + ks_ * 128);                      \
                mma8(acc[0][0][nt_], a0_.x, a0_.y, a0_.z, a0_.w, b01_.x, b01_.y); \
                mma8(acc[0][1][nt_], a1_.x, a1_.y, a1_.z, a1_.w, b01_.x, b01_.y); \
                mma8(acc[1][0][nt_], a0_.x, a0_.y, a0_.z, a0_.w, b01_.z, b01_.w); \
                mma8(acc[1][1][nt_], a1_.x, a1_.y, a1_.z, a1_.w, b01_.z, b01_.w); \
                mma8(acc[2][0][nt_], a0_.x, a0_.y, a0_.z, a0_.w, b23_.x, b23_.y); \
                mma8(acc[2][1][nt_], a1_.x, a1_.y, a1_.z, a1_.w, b23_.x, b23_.y); \
                mma8(acc[3][0][nt_], a0_.x, a0_.y, a0_.z, a0_.w, b23_.z, b23_.w); \
                mma8(acc[3][1][nt_], a1_.x, a1_.y, a1_.z, a1_.w, b23_.z, b23_.w); \
            }                                                                 \
        }                                                                     \
    } while (0)

#define WAIT1() asm volatile("cp.async.wait_group 1;" ::: "memory")
#define WAIT0() asm volatile("cp.async.wait_group 0;" ::: "memory")

    ISSUE(0);
    ISSUE(1);

    for (int su = 0; su < 21; su++) {
        WAIT1(); __syncthreads();
        MMA_BLOCK(0);
        ISSUE(2);
        WAIT1(); __syncthreads();
        MMA_BLOCK(1);
        ISSUE(0);
        WAIT1(); __syncthreads();
        MMA_BLOCK(2);
        if (su < 20) ISSUE(1);
    }
    WAIT0(); __syncthreads();
    MMA_BLOCK(0);

    // ---- fused LSTM epilogue (MUFU tanh) ----
    const int gid = lid >> 2;
    const int tig = lid & 3;
    const float* bias_s = (const float*)(smw + 3 * STAGE_WORDS);
    float* outH = out;
    float* outC = out + (size_t)BATCH * HDIM;
    const int mblk = mb * 128;
    const int nblk = nb * 32;

#pragma unroll
    for (int nt = 0; nt < 2; nt++) {
        const int colloc = warpN * 16 + nt * 8 + tig * 2;
        const float bF0 = bias_s[0 * 32 + colloc], bF1 = bias_s[0 * 32 + colloc + 1];
        const float bI0 = bias_s[1 * 32 + colloc], bI1 = bias_s[1 * 32 + colloc + 1];
        const float bG0 = bias_s[2 * 32 + colloc], bG1 = bias_s[2 * 32 + colloc + 1];
        const float bO0 = bias_s[3 * 32 + colloc], bO1 = bias_s[3 * 32 + colloc + 1];
#pragma unroll
        for (int mt = 0; mt < 2; mt++)
#pragma unroll
            for (int p = 0; p < 2; p++) {
                const int m = mblk + warpM * 32 + mt * 16 + gid + 8 * p;
                const size_t base = (size_t)m * HDIM + nblk + colloc;
                const float2 cc = *(const float2*)&c[base];
                const int e = p * 2;
                const float pf0 = acc[0][mt][nt][e] + bF0, pf1 = acc[0][mt][nt][e + 1] + bF1;
                const float pi0 = acc[1][mt][nt][e] + bI0, pi1 = acc[1][mt][nt][e + 1] + bI1;
                const float pg0 = acc[2][mt][nt][e] + bG0, pg1 = acc[2][mt][nt][e + 1] + bG1;
                const float po0 = acc[3][mt][nt][e] + bO0, po1 = acc[3][mt][nt][e + 1] + bO1;
                const float f0 = sig_ap(pf0), f1 = sig_ap(pf1);
                const float i0 = sig_ap(pi0), i1 = sig_ap(pi1);
                const float g0 = tanh_ap(pg0), g1 = tanh_ap(pg1);
                const float o0 = sig_ap(po0), o1 = sig_ap(po1);
                const float cn0 = fmaf(f0, cc.x, i0 * g0);
                const float cn1 = fmaf(f1, cc.y, i1 * g1);
                *(float2*)&outH[base] = make_float2(o0 * tanh_ap(cn0), o1 * tanh_ap(cn1));
                *(float2*)&outC[base] = make_float2(cn0, cn1);
            }
    }
}

extern "C" void kernel_launch(void* const* d_in, const int* in_sizes, int n_in,
                              void* d_out, int out_size)
{
    const float* x    = (const float*)d_in[0];
    const float* h    = (const float*)d_in[1];
    const float* c    = (const float*)d_in[2];
    const float* wf_i = (const float*)d_in[3];
    const float* bf_i = (const float*)d_in[4];
    const float* wf_h = (const float*)d_in[5];
    const float* bf_h = (const float*)d_in[6];
    const float* wi_i = (const float*)d_in[7];
    const float* bi_i = (const float*)d_in[8];
    const float* wi_h = (const float*)d_in[9];
    const float* bi_h = (const float*)d_in[10];
    const float* wg_i = (const float*)d_in[11];
    const float* bg_i = (const float*)d_in[12];
    const float* wg_h = (const float*)d_in[13];
    const float* bg_h = (const float*)d_in[14];
    const float* wo_i = (const float*)d_in[15];
    const float* bo_i = (const float*)d_in[16];
    const float* wo_h = (const float*)d_in[17];
    const float* bo_h = (const float*)d_in[18];
    float* out = (float*)d_out;

    cudaFuncSetAttribute(lstm_main, cudaFuncAttributeMaxDynamicSharedMemorySize, SMEM_BYTES);

    prep_kernel<<<24576, 256>>>(x, h, wf_i, wf_h, wi_i, wi_h, wg_i, wg_h, wo_i, wo_h);

    dim3 grid(HDIM / 32, BATCH / 128);   // (32, 64)
    lstm_main<<<grid, 256, SMEM_BYTES>>>(c,
                                         bf_i, bf_h, bi_i, bi_h,
                                         bg_i, bg_h, bo_i, bo_h,
                                         out);
}